// round 6
// baseline (speedup 1.0000x reference)
#include <cuda_runtime.h>
#include <cstdint>

#define G_   2048
#define NPG  128
#define NN   (G_*NPG)       // 262144 nodes
#define INC  151
#define HID  64
#define NE   2097152
#define NEG_SLOPE 0.2f

// ---------------- device scratch ----------------
__device__ float g_h[(size_t)NN * HID];   // 64 MB
__device__ float g_as[NN];
__device__ float g_ad[NN];
__device__ int   g_deg[NN];
__device__ int   g_fill[NN];
__device__ int   g_off[NN];
__device__ int   g_bsum[1024];
__device__ int   g_csr[NE];

// packed f32x2 FMA (FFMA2): 2 fp32 FMA per issue slot, bitwise == 2x fmaf
#define FMA2(c, a, b) asm("fma.rn.f32x2 %0, %1, %2, %0;" : "+l"(c) : "l"(a), "l"(b))

// ---------------- K0: zero counters ----------------
__global__ void k_zero() {
    int i = blockIdx.x * blockDim.x + threadIdx.x;
    g_deg[i] = 0; g_fill[i] = 0;
}

// ---------------- K1: h = x @ W1 fp32 FFMA2 GEMM, fused att scores ----------
// Block tile 128(M) x 64(N), 128 threads (8 tx x 16 ty), microtile (4+4)x(4+4).
// sXd holds each x value DUPLICATED as {v,v} so A-pairs load with one LDS.
#define LDXD 130   // float2 units per k-row (128 + pad), 16B-aligned rows
#define LDW  68
__global__ __launch_bounds__(128) void k_gemm(const float* __restrict__ x,
                                              const float* __restrict__ W,
                                              const float* __restrict__ att_src,
                                              const float* __restrict__ att_dst) {
    __shared__ float2 sXd[16 * LDXD];   // [k][row] duplicated pairs
    __shared__ float  sW[16 * LDW];     // [k][col]
    int tid = threadIdx.x;
    int tx = tid & 7, ty = tid >> 3;
    int row0 = blockIdx.x * 128;

    unsigned long long acc2[8][4];
    #pragma unroll
    for (int i = 0; i < 8; i++)
        #pragma unroll
        for (int j = 0; j < 4; j++) acc2[i][j] = 0ULL;

    for (int c0 = 0; c0 < 160; c0 += 16) {
        // stage x chunk transposed + duplicated: sXd[k][r] = {v,v}
        {
            int c = tid & 15, rt = tid >> 4;
            int col = c0 + c;
            bool ok = (col < INC);
            #pragma unroll
            for (int p = 0; p < 16; p++) {
                int r = rt + p * 8;
                float v = ok ? x[(size_t)(row0 + r) * INC + col] : 0.f;
                sXd[c * LDXD + r] = make_float2(v, v);
            }
        }
        // stage W chunk: sW[k][n]
        {
            int n = tid & 63, kt = tid >> 6;
            #pragma unroll
            for (int p = 0; p < 8; p++) {
                int k = kt + p * 2;
                int kk = c0 + k;
                sW[k * LDW + n] = (kk < INC) ? W[kk * 64 + n] : 0.f;
            }
        }
        __syncthreads();
        #pragma unroll
        for (int k = 0; k < 16; k++) {
            // A pairs: rows ty*4..+3 and 64+ty*4..+3 (each {v,v})
            ulonglong2 A0 = *(const ulonglong2*)&sXd[k * LDXD + ty * 4];
            ulonglong2 A1 = *(const ulonglong2*)&sXd[k * LDXD + ty * 4 + 2];
            ulonglong2 A2 = *(const ulonglong2*)&sXd[k * LDXD + 64 + ty * 4];
            ulonglong2 A3 = *(const ulonglong2*)&sXd[k * LDXD + 64 + ty * 4 + 2];
            // B pairs: cols (tx*4..+3) and (32+tx*4..+3), naturally adjacent
            ulonglong2 B0 = *(const ulonglong2*)&sW[k * LDW + tx * 4];
            ulonglong2 B1 = *(const ulonglong2*)&sW[k * LDW + 32 + tx * 4];
            unsigned long long pa[8] = {A0.x, A0.y, A1.x, A1.y, A2.x, A2.y, A3.x, A3.y};
            unsigned long long pb[4] = {B0.x, B0.y, B1.x, B1.y};
            #pragma unroll
            for (int i = 0; i < 8; i++) {
                FMA2(acc2[i][0], pa[i], pb[0]);
                FMA2(acc2[i][1], pa[i], pb[1]);
                FMA2(acc2[i][2], pa[i], pb[2]);
                FMA2(acc2[i][3], pa[i], pb[3]);
            }
        }
        __syncthreads();
    }

    // attention vector slices for this thread's 8 columns
    float asv[8], adv[8];
    #pragma unroll
    for (int j = 0; j < 8; j++) {
        int cj = (j < 4) ? (tx * 4 + j) : (32 + tx * 4 + (j - 4));
        asv[j] = __ldg(&att_src[cj]);
        adv[j] = __ldg(&att_dst[cj]);
    }

    #pragma unroll
    for (int i = 0; i < 8; i++) {
        int r = row0 + ((i < 4) ? (ty * 4 + i) : (64 + ty * 4 + (i - 4)));
        float2 c01 = *(float2*)&acc2[i][0];
        float2 c23 = *(float2*)&acc2[i][1];
        float2 c45 = *(float2*)&acc2[i][2];
        float2 c67 = *(float2*)&acc2[i][3];
        float a[8] = {c01.x, c01.y, c23.x, c23.y, c45.x, c45.y, c67.x, c67.y};
        *(float4*)&g_h[(size_t)r * 64 + tx * 4]      = make_float4(a[0], a[1], a[2], a[3]);
        *(float4*)&g_h[(size_t)r * 64 + 32 + tx * 4] = make_float4(a[4], a[5], a[6], a[7]);
        float ps = 0.f, pd = 0.f;
        #pragma unroll
        for (int j = 0; j < 8; j++) {
            ps = fmaf(a[j], asv[j], ps);
            pd = fmaf(a[j], adv[j], pd);
        }
        #pragma unroll
        for (int o = 4; o; o >>= 1) {
            ps += __shfl_down_sync(0xFFFFFFFFu, ps, o, 8);
            pd += __shfl_down_sync(0xFFFFFFFFu, pd, o, 8);
        }
        if (tx == 0) { g_as[r] = ps; g_ad[r] = pd; }
    }
}

// ---------------- K2: in-degree histogram ----------------
__global__ void k_hist(const int* __restrict__ ei) {
    int e = blockIdx.x * blockDim.x + threadIdx.x;
    if (e < NE) atomicAdd(&g_deg[ei[NE + e]], 1);
}

// ---------------- K3: 2-level exclusive scan ----------------
__global__ void k_scanA() {
    int t = threadIdx.x;
    int i = blockIdx.x * 256 + t;
    int v = g_deg[i];
    int lane = t & 31, w = t >> 5;
    int x = v;
    #pragma unroll
    for (int d = 1; d < 32; d <<= 1) { int y = __shfl_up_sync(0xFFFFFFFFu, x, d); if (lane >= d) x += y; }
    __shared__ int wt[8];
    if (lane == 31) wt[w] = x;
    __syncthreads();
    if (t < 8) {
        int s = wt[t];
        int xs = s;
        #pragma unroll
        for (int d = 1; d < 8; d <<= 1) { int y = __shfl_up_sync(0xFFu, xs, d); if (t >= d) xs += y; }
        wt[t] = xs - s;
    }
    __syncthreads();
    int incl = x + wt[w];
    g_off[i] = incl - v;
    if (t == 255) g_bsum[blockIdx.x] = incl;
}

__global__ void k_scanB() {
    int t = threadIdx.x;
    int lane = t & 31, w = t >> 5;
    int v = g_bsum[t];
    int x = v;
    #pragma unroll
    for (int d = 1; d < 32; d <<= 1) { int y = __shfl_up_sync(0xFFFFFFFFu, x, d); if (lane >= d) x += y; }
    __shared__ int wt[32];
    if (lane == 31) wt[w] = x;
    __syncthreads();
    if (w == 0) {
        int s = wt[lane];
        int xs = s;
        #pragma unroll
        for (int d = 1; d < 32; d <<= 1) { int y = __shfl_up_sync(0xFFFFFFFFu, xs, d); if (lane >= d) xs += y; }
        wt[lane] = xs - s;
    }
    __syncthreads();
    g_bsum[t] = x - v + wt[w];
}

__global__ void k_scanC() {
    int i = blockIdx.x * 256 + threadIdx.x;
    g_off[i] += g_bsum[i >> 8];
}

// ---------------- K4: scatter into CSR ----------------
__global__ void k_scatter(const int* __restrict__ ei) {
    int e = blockIdx.x * blockDim.x + threadIdx.x;
    if (e >= NE) return;
    int dst = ei[NE + e];
    int src = ei[e];
    int p = g_off[dst] + atomicAdd(&g_fill[dst], 1);
    g_csr[p] = src;
}

// ---------------- K5: block-per-graph softmax agg + ReLU + linear + sigmoid ----
__global__ __launch_bounds__(256) void k_agg(const float* __restrict__ b1,
                                             const float* __restrict__ Wlin,
                                             const float* __restrict__ blin,
                                             float* __restrict__ out) {
    __shared__ float sh[128 * 64];        // graph's h tile, 32 KB
    __shared__ float s_as[128], s_ad[128];
    __shared__ float s_ex[8][64];
    __shared__ float s_part[8];
    int g = blockIdx.x;
    int tid = threadIdx.x, lane = tid & 31, wid = tid >> 5;
    int nbase = g * 128;

    {
        const float4* src4 = (const float4*)&g_h[(size_t)nbase * 64];
        float4* dst4 = (float4*)sh;
        #pragma unroll
        for (int i = tid; i < 128 * 16; i += 256) dst4[i] = src4[i];
        if (tid < 128) { s_as[tid] = g_as[nbase + tid]; s_ad[tid] = g_ad[nbase + tid]; }
    }
    __syncthreads();

    float2 bb = *(const float2*)&b1[lane * 2];
    float wsum = 0.f;

    for (int t = 0; t < 16; t++) {
        int ln = wid * 16 + t;
        int n  = nbase + ln;
        float ad_i = s_ad[ln];
        float a0 = s_as[ln] + ad_i;
        a0 = a0 >= 0.f ? a0 : NEG_SLOPE * a0;
        int deg = g_deg[n], start = g_off[n];

        float m = a0;
        for (int e = lane; e < deg; e += 32) {
            int s = g_csr[start + e] & 127;
            float a = s_as[s] + ad_i;
            a = a >= 0.f ? a : NEG_SLOPE * a;
            if (e < 64) s_ex[wid][e] = a;
            m = fmaxf(m, a);
        }
        #pragma unroll
        for (int o = 16; o; o >>= 1) m = fmaxf(m, __shfl_xor_sync(0xFFFFFFFFu, m, o));
        __syncwarp();

        float z = (lane == 0) ? __expf(a0 - m) : 0.f;
        for (int e = lane; e < deg; e += 32) {
            float a;
            if (e < 64) a = s_ex[wid][e];
            else { int s = g_csr[start + e] & 127; a = s_as[s] + ad_i; a = a >= 0.f ? a : NEG_SLOPE * a; }
            float ex = __expf(a - m);
            if (e < 64) s_ex[wid][e] = ex;
            z += ex;
        }
        #pragma unroll
        for (int o = 16; o; o >>= 1) z += __shfl_xor_sync(0xFFFFFFFFu, z, o);
        float invz = 1.f / z;
        __syncwarp();

        float w0 = __expf(a0 - m) * invz;
        float2 hme = *(const float2*)&sh[ln * 64 + lane * 2];
        float accx = w0 * hme.x, accy = w0 * hme.y;
        for (int e = 0; e < deg; e++) {
            int s = g_csr[start + e] & 127;
            float w;
            if (e < 64) w = s_ex[wid][e] * invz;
            else {
                float a = s_as[s] + ad_i; a = a >= 0.f ? a : NEG_SLOPE * a;
                w = __expf(a - m) * invz;
            }
            float2 hs = *(const float2*)&sh[s * 64 + lane * 2];
            accx = fmaf(w, hs.x, accx);
            accy = fmaf(w, hs.y, accy);
        }
        __syncwarp();

        float rx = fmaxf(accx + bb.x, 0.f);
        float ry = fmaxf(accy + bb.y, 0.f);
        float2 wl = *(const float2*)&Wlin[ln * 64 + lane * 2];
        float p = rx * wl.x + ry * wl.y;
        #pragma unroll
        for (int o = 16; o; o >>= 1) p += __shfl_xor_sync(0xFFFFFFFFu, p, o);
        wsum += p;
    }

    if (lane == 0) s_part[wid] = wsum;
    __syncthreads();
    if (tid == 0) {
        float l = blin[0];
        #pragma unroll
        for (int i = 0; i < 8; i++) l += s_part[i];
        out[g] = 1.f / (1.f + __expf(-l));
    }
}

// ---------------- launch ----------------
extern "C" void kernel_launch(void* const* d_in, const int* in_sizes, int n_in,
                              void* d_out, int out_size) {
    const float* x    = (const float*)d_in[0];
    const int*   ei   = (const int*)  d_in[1];
    const float* W1   = (const float*)d_in[2];
    const float* asv  = (const float*)d_in[3];
    const float* adv  = (const float*)d_in[4];
    const float* b1   = (const float*)d_in[5];
    const float* Wlin = (const float*)d_in[6];
    const float* blin = (const float*)d_in[7];
    float* out = (float*)d_out;

    static cudaStream_t s2 = nullptr;
    static cudaEvent_t ev0 = nullptr, ev1 = nullptr;
    if (!s2) {
        cudaStreamCreateWithFlags(&s2, cudaStreamNonBlocking);
        cudaEventCreateWithFlags(&ev0, cudaEventDisableTiming);
        cudaEventCreateWithFlags(&ev1, cudaEventDisableTiming);
    }

    k_zero<<<NN / 256, 256>>>();

    // fork: edge preprocessing on side stream, overlapped with GEMM
    cudaEventRecord(ev0, 0);
    cudaStreamWaitEvent(s2, ev0, 0);
    k_hist   <<<NE / 256, 256, 0, s2>>>(ei);
    k_scanA  <<<1024, 256, 0, s2>>>();
    k_scanB  <<<1, 1024, 0, s2>>>();
    k_scanC  <<<1024, 256, 0, s2>>>();
    k_scatter<<<NE / 256, 256, 0, s2>>>(ei);
    cudaEventRecord(ev1, s2);

    k_gemm<<<NN / 128, 128>>>(x, W1, asv, adv);

    // join
    cudaStreamWaitEvent(0, ev1, 0);
    k_agg<<<G_, 256>>>(b1, Wlin, blin, out);
}